// round 2
// baseline (speedup 1.0000x reference)
#include <cuda_runtime.h>

#define Nn 4
#define Pp 2048
#define Dd 512
#define Hh 8
#define HD 64
#define SCALE 0.044194173824159216f /* 1/sqrt(512) */

__device__ float g_q[Nn * Hh * Pp * HD];
__device__ float g_k[Nn * Hh * Pp * HD];
__device__ float g_v[Nn * Hh * Pp * HD];
__device__ float g_oh[Nn * Pp * Dd];
__device__ float g_woT[Dd * Dd];

// -------- Kernel 1: QKV projection --------------------------------------
__global__ void qkv_kernel(const float* __restrict__ x,
                           const float* __restrict__ Wq,
                           const float* __restrict__ Wk,
                           const float* __restrict__ Wv) {
    extern __shared__ float sm[];
    float* wq_s = sm;                // 64*65
    float* wk_s = wq_s + 64 * 65;
    float* wv_s = wk_s + 64 * 65;
    float* xs   = wv_s + 64 * 65;    // 32*64

    int t = threadIdx.x;
    for (int idx = t; idx < 4096; idx += 256) {
        int e = idx >> 6, d = idx & 63;
        wq_s[e * 65 + d] = Wq[idx];
        wk_s[e * 65 + d] = Wk[idx];
        wv_s[e * 65 + d] = Wv[idx];
    }
    size_t R0 = (size_t)blockIdx.x * 32;
    const float4* xg = (const float4*)(x + R0 * 64);
    float4* xs4 = (float4*)xs;
    xs4[t]       = xg[t];
    xs4[t + 256] = xg[t + 256];
    __syncthreads();

    int w = t >> 5, l = t & 31;
    float aq[4][2] = {}, ak[4][2] = {}, av[4][2] = {};
#pragma unroll 4
    for (int d = 0; d < 64; d++) {
        float xv[4];
#pragma unroll
        for (int i = 0; i < 4; i++) xv[i] = xs[(w * 4 + i) * 64 + d];
        float q0 = wq_s[l * 65 + d], q1 = wq_s[(l + 32) * 65 + d];
        float k0 = wk_s[l * 65 + d], k1 = wk_s[(l + 32) * 65 + d];
        float v0 = wv_s[l * 65 + d], v1 = wv_s[(l + 32) * 65 + d];
#pragma unroll
        for (int i = 0; i < 4; i++) {
            aq[i][0] += xv[i] * q0; aq[i][1] += xv[i] * q1;
            ak[i][0] += xv[i] * k0; ak[i][1] += xv[i] * k1;
            av[i][0] += xv[i] * v0; av[i][1] += xv[i] * v1;
        }
    }
#pragma unroll
    for (int i = 0; i < 4; i++) {
        int R = (int)R0 + w * 4 + i;           // R = ((n*P + p)*H + h)
        int n = R / (Pp * Hh);
        int rem = R % (Pp * Hh);
        int p = rem / Hh, h = rem % Hh;
        int base = ((n * Hh + h) * Pp + p) * HD;
        g_q[base + l] = aq[i][0]; g_q[base + l + 32] = aq[i][1];
        g_k[base + l] = ak[i][0]; g_k[base + l + 32] = ak[i][1];
        g_v[base + l] = av[i][0]; g_v[base + l + 32] = av[i][1];
    }
}

// -------- Kernel 2: energy + softmax -> normalized attention ------------
__global__ void attn_kernel(float* __restrict__ attn_out) {
    extern __shared__ float sm[];
    float* qs = sm;                  // [64][20] transposed Q (pad)
    float* ks = qs + 64 * 20;        // [64][256] transposed K chunk
    float* Es = ks + 64 * 256;       // [16][2048]
    float* rs = Es + 16 * 2048;      // [16]

    int t = threadIdx.x;
    int bx = blockIdx.x;
    int qt = bx & 127, h = (bx >> 7) & 7, n = bx >> 10;
    int nh = n * Hh + h;
    int q0 = qt * 16;

    const float* qg = g_q + ((size_t)nh * Pp + q0) * HD;
    const float* kg = g_k + (size_t)nh * Pp * HD;

    if (t < 16) rs[t] = 0.0f;
    {   // load Q tile transposed
        int r = t >> 4, dg = t & 15;
        float4 v = *(const float4*)(qg + r * 64 + dg * 4);
        qs[(4 * dg + 0) * 20 + r] = v.x;
        qs[(4 * dg + 1) * 20 + r] = v.y;
        qs[(4 * dg + 2) * 20 + r] = v.z;
        qs[(4 * dg + 3) * 20 + r] = v.w;
    }

    int rg = t >> 6;   // 4 q-rows per group
    int cg = t & 63;   // 4 k-cols per group
    float ps[4] = {0.f, 0.f, 0.f, 0.f};

    for (int ch = 0; ch < 8; ch++) {
        int c0 = ch * 256;
        __syncthreads();
        const float4* krow = (const float4*)(kg + (size_t)(c0 + t) * 64);
#pragma unroll
        for (int i = 0; i < 16; i++) {
            float4 v = krow[i];
            ks[(4 * i + 0) * 256 + t] = v.x;
            ks[(4 * i + 1) * 256 + t] = v.y;
            ks[(4 * i + 2) * 256 + t] = v.z;
            ks[(4 * i + 3) * 256 + t] = v.w;
        }
        __syncthreads();

        float acc[4][4] = {};
#pragma unroll 8
        for (int d = 0; d < 64; d++) {
            float4 qv = *(const float4*)(qs + d * 20 + 4 * rg);
            float4 kv = *(const float4*)(ks + d * 256 + 4 * cg);
            acc[0][0] += qv.x * kv.x; acc[0][1] += qv.x * kv.y;
            acc[0][2] += qv.x * kv.z; acc[0][3] += qv.x * kv.w;
            acc[1][0] += qv.y * kv.x; acc[1][1] += qv.y * kv.y;
            acc[1][2] += qv.y * kv.z; acc[1][3] += qv.y * kv.w;
            acc[2][0] += qv.z * kv.x; acc[2][1] += qv.z * kv.y;
            acc[2][2] += qv.z * kv.z; acc[2][3] += qv.z * kv.w;
            acc[3][0] += qv.w * kv.x; acc[3][1] += qv.w * kv.y;
            acc[3][2] += qv.w * kv.z; acc[3][3] += qv.w * kv.w;
        }
#pragma unroll
        for (int i = 0; i < 4; i++) {
            float4 ev;
            ev.x = __expf(acc[i][0] * SCALE);
            ev.y = __expf(acc[i][1] * SCALE);
            ev.z = __expf(acc[i][2] * SCALE);
            ev.w = __expf(acc[i][3] * SCALE);
            ps[i] += ev.x + ev.y + ev.z + ev.w;
            *(float4*)(Es + (size_t)(4 * rg + i) * 2048 + c0 + 4 * cg) = ev;
        }
    }

#pragma unroll
    for (int i = 0; i < 4; i++) {
        float v = ps[i];
#pragma unroll
        for (int o = 16; o > 0; o >>= 1) v += __shfl_xor_sync(0xffffffffu, v, o);
        if ((t & 31) == 0) atomicAdd(&rs[4 * rg + i], v);
    }
    __syncthreads();
    if (t < 16) rs[t] = 1.0f / rs[t];
    __syncthreads();

    float* aout = attn_out + ((size_t)nh * Pp + q0) * (size_t)Pp;
    for (int r = 0; r < 16; r++) {
        float inv = rs[r];
        const float4* er = (const float4*)(Es + (size_t)r * 2048);
        float4* orow = (float4*)(aout + (size_t)r * Pp);
#pragma unroll
        for (int ii = 0; ii < 2; ii++) {
            float4 v = er[t + ii * 256];
            v.x *= inv; v.y *= inv; v.z *= inv; v.w *= inv;
            orow[t + ii * 256] = v;
        }
    }
}

// -------- Kernel 3: oh = attention @ V ----------------------------------
__global__ void av_kernel(const float* __restrict__ attn) {
    __shared__ float As[64 * 68];  // [kc][row] transposed
    __shared__ float Bs[64 * 68];  // [kc][hd]
    int t = threadIdx.x;
    int bx = blockIdx.x;
    int qt = bx & 31, h = (bx >> 5) & 7, n = bx >> 8;
    int nh = n * Hh + h;
    int q0 = qt * 64;

    const float* ag = attn + ((size_t)nh * Pp + q0) * (size_t)Pp;
    const float* vg = g_v + (size_t)nh * Pp * HD;

    int ty = t >> 4, tx = t & 15;
    float acc[4][4] = {};

    for (int kc0 = 0; kc0 < Pp; kc0 += 64) {
        __syncthreads();
#pragma unroll
        for (int i = 0; i < 4; i++) {
            int f = t + i * 256;
            int r = f >> 4, kgp = f & 15;
            float4 a = *(const float4*)(ag + (size_t)r * Pp + kc0 + 4 * kgp);
            As[(4 * kgp + 0) * 68 + r] = a.x;
            As[(4 * kgp + 1) * 68 + r] = a.y;
            As[(4 * kgp + 2) * 68 + r] = a.z;
            As[(4 * kgp + 3) * 68 + r] = a.w;
            float4 b = *(const float4*)(vg + (size_t)(kc0 + r) * 64 + 4 * kgp);
            *(float4*)(&Bs[r * 68 + 4 * kgp]) = b;
        }
        __syncthreads();
#pragma unroll 8
        for (int kc = 0; kc < 64; kc++) {
            float4 a = *(const float4*)(&As[kc * 68 + 4 * ty]);
            float4 b = *(const float4*)(&Bs[kc * 68 + 4 * tx]);
            acc[0][0] += a.x * b.x; acc[0][1] += a.x * b.y; acc[0][2] += a.x * b.z; acc[0][3] += a.x * b.w;
            acc[1][0] += a.y * b.x; acc[1][1] += a.y * b.y; acc[1][2] += a.y * b.z; acc[1][3] += a.y * b.w;
            acc[2][0] += a.z * b.x; acc[2][1] += a.z * b.y; acc[2][2] += a.z * b.z; acc[2][3] += a.z * b.w;
            acc[3][0] += a.w * b.x; acc[3][1] += a.w * b.y; acc[3][2] += a.w * b.z; acc[3][3] += a.w * b.w;
        }
    }
#pragma unroll
    for (int i = 0; i < 4; i++) {
        int row = q0 + 4 * ty + i;
        float4 v = make_float4(acc[i][0], acc[i][1], acc[i][2], acc[i][3]);
        *(float4*)(g_oh + ((size_t)n * Pp + row) * Dd + h * HD + 4 * tx) = v;
    }
}

// -------- Kernel 4a: Wo transpose ---------------------------------------
__global__ void woT_kernel(const float* __restrict__ Wo) {
    __shared__ float tile[32][33];
    int x0 = blockIdx.x * 32, y0 = blockIdx.y * 32;
    int tx = threadIdx.x, ty = threadIdx.y;
#pragma unroll
    for (int i = 0; i < 32; i += 8)
        tile[ty + i][tx] = Wo[(size_t)(y0 + ty + i) * Dd + x0 + tx];
    __syncthreads();
#pragma unroll
    for (int i = 0; i < 32; i += 8)
        g_woT[(size_t)(x0 + ty + i) * Dd + y0 + tx] = tile[tx][ty + i];
}

// -------- Kernel 4b: out = oh @ Wo^T + bo -------------------------------
__global__ void out_kernel(const float* __restrict__ bo, float* __restrict__ out) {
    __shared__ float As[64 * 68];
    __shared__ float Bs[64 * 68];
    int t = threadIdx.x;
    int ct = blockIdx.x & 7;
    int rt = blockIdx.x >> 3;
    int r0 = rt * 64, e0 = ct * 64;
    int ty = t >> 4, tx = t & 15;
    float acc[4][4] = {};

    for (int kc0 = 0; kc0 < Dd; kc0 += 64) {
        __syncthreads();
#pragma unroll
        for (int i = 0; i < 4; i++) {
            int f = t + i * 256;
            int r = f >> 4, kgp = f & 15;
            float4 a = *(const float4*)(g_oh + (size_t)(r0 + r) * Dd + kc0 + 4 * kgp);
            As[(4 * kgp + 0) * 68 + r] = a.x;
            As[(4 * kgp + 1) * 68 + r] = a.y;
            As[(4 * kgp + 2) * 68 + r] = a.z;
            As[(4 * kgp + 3) * 68 + r] = a.w;
            float4 b = *(const float4*)(g_woT + (size_t)(kc0 + r) * Dd + e0 + 4 * kgp);
            *(float4*)(&Bs[r * 68 + 4 * kgp]) = b;
        }
        __syncthreads();
#pragma unroll 8
        for (int kc = 0; kc < 64; kc++) {
            float4 a = *(const float4*)(&As[kc * 68 + 4 * ty]);
            float4 b = *(const float4*)(&Bs[kc * 68 + 4 * tx]);
            acc[0][0] += a.x * b.x; acc[0][1] += a.x * b.y; acc[0][2] += a.x * b.z; acc[0][3] += a.x * b.w;
            acc[1][0] += a.y * b.x; acc[1][1] += a.y * b.y; acc[1][2] += a.y * b.z; acc[1][3] += a.y * b.w;
            acc[2][0] += a.z * b.x; acc[2][1] += a.z * b.y; acc[2][2] += a.z * b.z; acc[2][3] += a.z * b.w;
            acc[3][0] += a.w * b.x; acc[3][1] += a.w * b.y; acc[3][2] += a.w * b.z; acc[3][3] += a.w * b.w;
        }
    }
    float4 bias = *(const float4*)(bo + e0 + 4 * tx);
#pragma unroll
    for (int i = 0; i < 4; i++) {
        float4 v = make_float4(acc[i][0] + bias.x, acc[i][1] + bias.y,
                               acc[i][2] + bias.z, acc[i][3] + bias.w);
        *(float4*)(out + (size_t)(r0 + 4 * ty + i) * Dd + e0 + 4 * tx) = v;
    }
}

extern "C" void kernel_launch(void* const* d_in, const int* in_sizes, int n_in,
                              void* d_out, int out_size) {
    const float* xyz = (const float*)d_in[0];
    const float* Wq  = (const float*)d_in[1];
    const float* Wk  = (const float*)d_in[2];
    const float* Wv  = (const float*)d_in[3];
    const float* Wo  = (const float*)d_in[4];
    const float* bo  = (const float*)d_in[5];
    float* out  = (float*)d_out;                       // (4,2048,512)
    float* attn = (float*)d_out + (size_t)Nn * Pp * Dd; // (4,8,2048,2048)

    static const int QKV_SMEM  = (3 * 64 * 65 + 32 * 64) * 4;      // 58112
    static const int ATTN_SMEM = (64 * 20 + 64 * 256 + 16 * 2048 + 16) * 4; // 201792
    cudaFuncSetAttribute(qkv_kernel,  cudaFuncAttributeMaxDynamicSharedMemorySize, QKV_SMEM);
    cudaFuncSetAttribute(attn_kernel, cudaFuncAttributeMaxDynamicSharedMemorySize, ATTN_SMEM);

    woT_kernel<<<dim3(16, 16), dim3(32, 8)>>>(Wo);
    qkv_kernel<<<(Nn * Pp * Hh) / 32, 256, QKV_SMEM>>>(xyz, Wq, Wk, Wv);
    attn_kernel<<<Nn * Hh * (Pp / 16), 256, ATTN_SMEM>>>(attn);
    av_kernel<<<Nn * Hh * (Pp / 64), 256>>>(attn);
    out_kernel<<<(Nn * Pp / 64) * (Dd / 64), 256>>>(bo, out);
}

// round 5
// speedup vs baseline: 2.7031x; 2.7031x over previous
#include <cuda_runtime.h>
#include <cuda_fp16.h>
#include <cstdint>

#define Nn 4
#define Pp 2048
#define Dd 512
#define Hh 8
#define HD 64
// sqrt(1/sqrt(512) * log2(e)) — folded into both q and k so QK^T lands in log2 domain
#define SQS 0.25250490f

// ---- scratch (__device__ globals; no allocations allowed) ----
__device__ __half g_qhi[Nn * Hh * Pp * HD];
__device__ __half g_qlo[Nn * Hh * Pp * HD];
__device__ __half g_khi[Nn * Hh * Pp * HD];
__device__ __half g_klo[Nn * Hh * Pp * HD];
__device__ __half g_vhi[Nn * Hh * Pp * HD];
__device__ __half g_vlo[Nn * Hh * Pp * HD];
__device__ float g_oh[Nn * Pp * Dd];
__device__ float g_woT[Dd * Dd];
__device__ float g_inv[Nn * Hh * Pp];

// ---- helpers ----
static __device__ __forceinline__ uint32_t s2u(const void* p) {
    uint32_t a;
    asm("{ .reg .u64 t; cvta.to.shared.u64 t, %1; cvt.u32.u64 %0, t; }" : "=r"(a) : "l"(p));
    return a;
}
static __device__ __forceinline__ void ldsm4(uint32_t* r, uint32_t a) {
    asm volatile("ldmatrix.sync.aligned.m8n8.x4.shared.b16 {%0,%1,%2,%3}, [%4];"
                 : "=r"(r[0]), "=r"(r[1]), "=r"(r[2]), "=r"(r[3]) : "r"(a));
}
static __device__ __forceinline__ void ldsm4t(uint32_t* r, uint32_t a) {
    asm volatile("ldmatrix.sync.aligned.m8n8.x4.trans.shared.b16 {%0,%1,%2,%3}, [%4];"
                 : "=r"(r[0]), "=r"(r[1]), "=r"(r[2]), "=r"(r[3]) : "r"(a));
}
static __device__ __forceinline__ void mma16816(float* c, const uint32_t* a,
                                                uint32_t b0, uint32_t b1) {
    asm volatile(
        "mma.sync.aligned.m16n8k16.row.col.f32.f16.f16.f32 "
        "{%0,%1,%2,%3}, {%4,%5,%6,%7}, {%8,%9}, {%0,%1,%2,%3};"
        : "+f"(c[0]), "+f"(c[1]), "+f"(c[2]), "+f"(c[3])
        : "r"(a[0]), "r"(a[1]), "r"(a[2]), "r"(a[3]), "r"(b0), "r"(b1));
}
// 2^t via MUFU
static __device__ __forceinline__ float ex2m(float t) {
    float r;
    asm("ex2.approx.f32 %0, %1;" : "=f"(r) : "f"(t));
    return r;
}
// 2^t via fp32 poly (FMA pipe). |t| < ~16. rel err ~4e-5.
static __device__ __forceinline__ float ex2p(float t) {
    const float MAGIC = 12582912.0f; // 1.5 * 2^23
    float r = __fadd_rn(t, MAGIC);
    float f = __fsub_rn(t, __fsub_rn(r, MAGIC)); // t - round(t), in [-0.5, 0.5]
    float p = fmaf(f, fmaf(f, fmaf(f, fmaf(f, 0.00961813f, 0.05550411f),
                                   0.24022651f), 0.69314718f), 1.0f);
    return __int_as_float(__float_as_int(p) + (__float_as_int(r) << 23));
}

// ---- Kernel 1: QKV projection -> fp16 hi/lo splits (q,k prescaled) -----
__global__ void qkv_kernel(const float* __restrict__ x,
                           const float* __restrict__ Wq,
                           const float* __restrict__ Wk,
                           const float* __restrict__ Wv) {
    extern __shared__ float sq[];
    float* wq_s = sq;
    float* wk_s = wq_s + 64 * 65;
    float* wv_s = wk_s + 64 * 65;
    float* xs   = wv_s + 64 * 65;

    int t = threadIdx.x;
    for (int idx = t; idx < 4096; idx += 256) {
        int e = idx >> 6, d = idx & 63;
        wq_s[e * 65 + d] = Wq[idx];
        wk_s[e * 65 + d] = Wk[idx];
        wv_s[e * 65 + d] = Wv[idx];
    }
    size_t R0 = (size_t)blockIdx.x * 32;
    const float4* xg = (const float4*)(x + R0 * 64);
    float4* xs4 = (float4*)xs;
    xs4[t]       = xg[t];
    xs4[t + 256] = xg[t + 256];
    __syncthreads();

    int w = t >> 5, l = t & 31;
    float aq[4][2] = {}, ak[4][2] = {}, av[4][2] = {};
#pragma unroll 4
    for (int d = 0; d < 64; d++) {
        float xv[4];
#pragma unroll
        for (int i = 0; i < 4; i++) xv[i] = xs[(w * 4 + i) * 64 + d];
        float q0 = wq_s[l * 65 + d], q1 = wq_s[(l + 32) * 65 + d];
        float k0 = wk_s[l * 65 + d], k1 = wk_s[(l + 32) * 65 + d];
        float v0 = wv_s[l * 65 + d], v1 = wv_s[(l + 32) * 65 + d];
#pragma unroll
        for (int i = 0; i < 4; i++) {
            aq[i][0] += xv[i] * q0; aq[i][1] += xv[i] * q1;
            ak[i][0] += xv[i] * k0; ak[i][1] += xv[i] * k1;
            av[i][0] += xv[i] * v0; av[i][1] += xv[i] * v1;
        }
    }
#pragma unroll
    for (int i = 0; i < 4; i++) {
        int R = (int)R0 + w * 4 + i;
        int n = R / (Pp * Hh);
        int rem = R % (Pp * Hh);
        int p = rem / Hh, h = rem % Hh;
        size_t base = ((size_t)(n * Hh + h) * Pp + p) * HD;
#pragma unroll
        for (int c = 0; c < 2; c++) {
            size_t ix = base + l + c * 32;
            float vq = aq[i][c] * SQS;
            float vk = ak[i][c] * SQS;
            float vv = av[i][c];
            __half hq = __float2half_rn(vq);
            __half hk = __float2half_rn(vk);
            __half hv = __float2half_rn(vv);
            g_qhi[ix] = hq; g_qlo[ix] = __float2half_rn(vq - __half2float(hq));
            g_khi[ix] = hk; g_klo[ix] = __float2half_rn(vk - __half2float(hk));
            g_vhi[ix] = hv; g_vlo[ix] = __float2half_rn(vv - __half2float(hv));
        }
    }
}

// ---- Kernel 2: fused HMMA attention ------------------------------------
// CTA = 64 q-rows of one (n,h). 128 threads = 4 warps, warp m = 16.
// smem rows padded to 72 halves (144B) -> conflict-free STS + ldmatrix.
#define SROW 72

__global__ void __launch_bounds__(128, 3) attn_hmma_kernel(float* __restrict__ attn_out) {
    extern __shared__ __half sh[];
    __half* sKhi = sh;
    __half* sKlo = sh + 128 * SROW;
    __half* sVhi = sh + 2 * 128 * SROW;
    __half* sVlo = sh + 3 * 128 * SROW;
    uint32_t bKhi = s2u(sKhi), bKlo = s2u(sKlo), bVhi = s2u(sVhi), bVlo = s2u(sVlo);

    int t = threadIdx.x;
    int w = t >> 5, l = t & 31;
    int bx = blockIdx.x;
    int qt = bx & 31, h = (bx >> 5) & 7, n = bx >> 8;
    int nh = n * Hh + h;
    int q0 = qt * 64;

    int g = l >> 2, tq = l & 3;

    // ---- stage Q tile (64 rows) into K smem area, build A-frags ----
    {
        const __half* qh = g_qhi + ((size_t)nh * Pp + q0) * HD;
        const __half* ql = g_qlo + ((size_t)nh * Pp + q0) * HD;
#pragma unroll
        for (int i = 0; i < 4; i++) {
            int idx = t + i * 128;
            int row = idx >> 3, cg = idx & 7;
            *(uint4*)(sKhi + row * SROW + cg * 8) = *(const uint4*)(qh + row * 64 + cg * 8);
            *(uint4*)(sKlo + row * SROW + cg * 8) = *(const uint4*)(ql + row * 64 + cg * 8);
        }
    }
    __syncthreads();
    uint32_t qfh[4][4], qfl[4][4];
    {
        int arow = w * 16 + (l & 7) + ((l >> 3) & 1) * 8;
        int acol = (l >> 4) * 8;
#pragma unroll
        for (int s = 0; s < 4; s++) {
            uint32_t off = (uint32_t)((arow * SROW + s * 16 + acol) * 2);
            ldsm4(qfh[s], bKhi + off);
            ldsm4(qfl[s], bKlo + off);
        }
    }
    __syncthreads();

    float dacc[8][4];
#pragma unroll
    for (int i = 0; i < 8; i++)
#pragma unroll
        for (int j = 0; j < 4; j++) dacc[i][j] = 0.0f;
    float rs0 = 0.0f, rs1 = 0.0f;

    const __half* kgh = g_khi + (size_t)nh * Pp * HD;
    const __half* kgl = g_klo + (size_t)nh * Pp * HD;
    const __half* vgh = g_vhi + (size_t)nh * Pp * HD;
    const __half* vgl = g_vlo + (size_t)nh * Pp * HD;

    int rowE0 = q0 + w * 16 + g;
    float* aslab = attn_out + (size_t)nh * Pp * (size_t)Pp;

    for (int c = 0; c < 16; c++) {
        int c0 = c * 128;
        // load K,V chunk (hi/lo) into smem
#pragma unroll
        for (int i = 0; i < 8; i++) {
            int idx = t + i * 128;
            int row = idx >> 3, cg = idx & 7;
            size_t go = (size_t)(c0 + row) * 64 + cg * 8;
            int so = row * SROW + cg * 8;
            *(uint4*)(sKhi + so) = *(const uint4*)(kgh + go);
            *(uint4*)(sKlo + so) = *(const uint4*)(kgl + go);
            *(uint4*)(sVhi + so) = *(const uint4*)(vgh + go);
            *(uint4*)(sVlo + so) = *(const uint4*)(vgl + go);
        }
        __syncthreads();

#pragma unroll
        for (int nhf = 0; nhf < 2; nhf++) {
            // ---- QK^T for 64 kv cols ----
            float cc[8][4];
#pragma unroll
            for (int i = 0; i < 8; i++)
#pragma unroll
                for (int j2 = 0; j2 < 4; j2++) cc[i][j2] = 0.0f;

#pragma unroll
            for (int j = 0; j < 8; j++) {
                int lrow = nhf * 64 + j * 8 + (l & 7);
                int lcol = ((l >> 3) & 3) * 8;
                uint32_t off = (uint32_t)((lrow * SROW + lcol) * 2);
                uint32_t kh[4], kh2[4], kl[4], kl2[4];
                ldsm4(kh, bKhi + off);
                ldsm4(kh2, bKhi + off + 64);
                ldsm4(kl, bKlo + off);
                ldsm4(kl2, bKlo + off + 64);
#pragma unroll
                for (int s = 0; s < 4; s++) {
                    uint32_t bh0 = (s < 2) ? kh[(s & 1) * 2]     : kh2[(s & 1) * 2];
                    uint32_t bh1 = (s < 2) ? kh[(s & 1) * 2 + 1] : kh2[(s & 1) * 2 + 1];
                    uint32_t bl0 = (s < 2) ? kl[(s & 1) * 2]     : kl2[(s & 1) * 2];
                    uint32_t bl1 = (s < 2) ? kl[(s & 1) * 2 + 1] : kl2[(s & 1) * 2 + 1];
                    mma16816(cc[j], qfh[s], bh0, bh1);
                    mma16816(cc[j], qfh[s], bl0, bl1);
                    mma16816(cc[j], qfl[s], bh0, bh1);
                }
            }

            // ---- exp epilogue: E store + P frags ----
            uint32_t phi_[4][4], plo_[4][4];
#pragma unroll
            for (int j = 0; j < 8; j++) {
                float v0 = ex2m(cc[j][0]);
                float v1 = ex2m(cc[j][1]);
                float v2 = (j & 1) ? ex2p(cc[j][2]) : ex2m(cc[j][2]);
                float v3 = ex2p(cc[j][3]);
                rs0 += v0 + v1;
                rs1 += v2 + v3;
                int col = c0 + nhf * 64 + j * 8 + 2 * tq;
                *(float2*)(aslab + (size_t)rowE0 * Pp + col)       = make_float2(v0, v1);
                *(float2*)(aslab + (size_t)(rowE0 + 8) * Pp + col) = make_float2(v2, v3);
                __half2 h01 = __floats2half2_rn(v0, v1);
                __half2 h23 = __floats2half2_rn(v2, v3);
                float2 f01 = __half22float2(h01);
                float2 f23 = __half22float2(h23);
                __half2 l01 = __floats2half2_rn(v0 - f01.x, v1 - f01.y);
                __half2 l23 = __floats2half2_rn(v2 - f23.x, v3 - f23.y);
                int s = j >> 1, rp = (j & 1) * 2;
                phi_[s][rp]     = *(uint32_t*)&h01;
                phi_[s][rp + 1] = *(uint32_t*)&h23;
                plo_[s][rp]     = *(uint32_t*)&l01;
                plo_[s][rp + 1] = *(uint32_t*)&l23;
            }

            // ---- AV accumulate ----
#pragma unroll
            for (int s = 0; s < 4; s++) {
                int lrow = nhf * 64 + s * 16 + (l & 7) + ((l >> 3) & 1) * 8;
#pragma unroll
                for (int djp = 0; djp < 4; djp++) {
                    int dj = djp * 2;
                    int lcol = dj * 8 + (l >> 4) * 8;
                    uint32_t off = (uint32_t)((lrow * SROW + lcol) * 2);
                    uint32_t vh[4], vl[4];
                    ldsm4t(vh, bVhi + off);
                    ldsm4t(vl, bVlo + off);
                    mma16816(dacc[dj], phi_[s], vh[0], vh[1]);
                    mma16816(dacc[dj], phi_[s], vl[0], vl[1]);
                    mma16816(dacc[dj], plo_[s], vh[0], vh[1]);
                    mma16816(dacc[dj + 1], phi_[s], vh[2], vh[3]);
                    mma16816(dacc[dj + 1], phi_[s], vl[2], vl[3]);
                    mma16816(dacc[dj + 1], plo_[s], vh[2], vh[3]);
                }
            }
        }
        __syncthreads();
    }

    // ---- finalize: rowsums, inv, oh store ----
    rs0 += __shfl_xor_sync(0xffffffffu, rs0, 1);
    rs0 += __shfl_xor_sync(0xffffffffu, rs0, 2);
    rs1 += __shfl_xor_sync(0xffffffffu, rs1, 1);
    rs1 += __shfl_xor_sync(0xffffffffu, rs1, 2);
    float inv0 = 1.0f / rs0, inv1 = 1.0f / rs1;
    if (tq == 0) {
        g_inv[nh * Pp + rowE0]     = inv0;
        g_inv[nh * Pp + rowE0 + 8] = inv1;
    }
    float* op0 = g_oh + ((size_t)n * Pp + rowE0) * Dd + h * HD;
    float* op1 = g_oh + ((size_t)n * Pp + rowE0 + 8) * Dd + h * HD;
#pragma unroll
    for (int dj = 0; dj < 8; dj++) {
        int cold = dj * 8 + 2 * tq;
        *(float2*)(op0 + cold) = make_float2(dacc[dj][0] * inv0, dacc[dj][1] * inv0);
        *(float2*)(op1 + cold) = make_float2(dacc[dj][2] * inv1, dacc[dj][3] * inv1);
    }
}

// ---- Kernel 3: normalize attention buffer ------------------------------
__global__ void norm_kernel(float* __restrict__ attn) {
    size_t i = (size_t)blockIdx.x * 256 + threadIdx.x;  // float4 index
    float inv = g_inv[i >> 9];
    float4* a4 = (float4*)attn;
    float4 v = a4[i];
    v.x *= inv; v.y *= inv; v.z *= inv; v.w *= inv;
    a4[i] = v;
}

// ---- Kernel 4a: Wo transpose -------------------------------------------
__global__ void woT_kernel(const float* __restrict__ Wo) {
    __shared__ float tile[32][33];
    int x0 = blockIdx.x * 32, y0 = blockIdx.y * 32;
    int tx = threadIdx.x, ty = threadIdx.y;
#pragma unroll
    for (int i = 0; i < 32; i += 8)
        tile[ty + i][tx] = Wo[(size_t)(y0 + ty + i) * Dd + x0 + tx];
    __syncthreads();
#pragma unroll
    for (int i = 0; i < 32; i += 8)
        g_woT[(size_t)(x0 + ty + i) * Dd + y0 + tx] = tile[tx][ty + i];
}

// ---- Kernel 4b: out = oh @ Wo^T + bo -----------------------------------
__global__ void out_kernel(const float* __restrict__ bo, float* __restrict__ out) {
    __shared__ float As[64 * 68];
    __shared__ float Bs[64 * 68];
    int t = threadIdx.x;
    int ct = blockIdx.x & 7;
    int rt = blockIdx.x >> 3;
    int r0 = rt * 64, e0 = ct * 64;
    int ty = t >> 4, tx = t & 15;
    float acc[4][4] = {};

    for (int kc0 = 0; kc0 < Dd; kc0 += 64) {
        __syncthreads();
#pragma unroll
        for (int i = 0; i < 4; i++) {
            int f = t + i * 256;
            int r = f >> 4, kgp = f & 15;
            float4 a = *(const float4*)(g_oh + (size_t)(r0 + r) * Dd + kc0 + 4 * kgp);
            As[(4 * kgp + 0) * 68 + r] = a.x;
            As[(4 * kgp + 1) * 68 + r] = a.y;
            As[(4 * kgp + 2) * 68 + r] = a.z;
            As[(4 * kgp + 3) * 68 + r] = a.w;
            float4 b = *(const float4*)(g_woT + (size_t)(kc0 + r) * Dd + e0 + 4 * kgp);
            *(float4*)(&Bs[r * 68 + 4 * kgp]) = b;
        }
        __syncthreads();
#pragma unroll 8
        for (int kc = 0; kc < 64; kc++) {
            float4 a = *(const float4*)(&As[kc * 68 + 4 * ty]);
            float4 b = *(const float4*)(&Bs[kc * 68 + 4 * tx]);
            acc[0][0] += a.x * b.x; acc[0][1] += a.x * b.y; acc[0][2] += a.x * b.z; acc[0][3] += a.x * b.w;
            acc[1][0] += a.y * b.x; acc[1][1] += a.y * b.y; acc[1][2] += a.y * b.z; acc[1][3] += a.y * b.w;
            acc[2][0] += a.z * b.x; acc[2][1] += a.z * b.y; acc[2][2] += a.z * b.z; acc[2][3] += a.z * b.w;
            acc[3][0] += a.w * b.x; acc[3][1] += a.w * b.y; acc[3][2] += a.w * b.z; acc[3][3] += a.w * b.w;
        }
    }
    float4 bias = *(const float4*)(bo + e0 + 4 * tx);
#pragma unroll
    for (int i = 0; i < 4; i++) {
        float4 v = make_float4(acc[i][0] + bias.x, acc[i][1] + bias.y,
                               acc[i][2] + bias.z, acc[i][3] + bias.w);
        *(float4*)(out + (size_t)(r0 + 4 * ty + i) * Dd + e0 + 4 * tx) = v;
    }
}

extern "C" void kernel_launch(void* const* d_in, const int* in_sizes, int n_in,
                              void* d_out, int out_size) {
    const float* xyz = (const float*)d_in[0];
    const float* Wq  = (const float*)d_in[1];
    const float* Wk  = (const float*)d_in[2];
    const float* Wv  = (const float*)d_in[3];
    const float* Wo  = (const float*)d_in[4];
    const float* bo  = (const float*)d_in[5];
    float* out  = (float*)d_out;                          // (4,2048,512)
    float* attn = (float*)d_out + (size_t)Nn * Pp * Dd;   // (4,8,2048,2048)

    static const int QKV_SMEM  = (3 * 64 * 65 + 32 * 64) * 4;
    static const int ATTN_SMEM = 4 * 128 * SROW * 2;      // 73728 B
    cudaFuncSetAttribute(qkv_kernel, cudaFuncAttributeMaxDynamicSharedMemorySize, QKV_SMEM);
    cudaFuncSetAttribute(attn_hmma_kernel, cudaFuncAttributeMaxDynamicSharedMemorySize, ATTN_SMEM);

    woT_kernel<<<dim3(16, 16), dim3(32, 8)>>>(Wo);
    qkv_kernel<<<(Nn * Pp * Hh) / 32, 256, QKV_SMEM>>>(xyz, Wq, Wk, Wv);
    attn_hmma_kernel<<<Nn * Hh * (Pp / 64), 128, ATTN_SMEM>>>(attn);
    norm_kernel<<<(int)(((size_t)Nn * Hh * Pp * Pp) / 4 / 256), 256>>>(attn);
    out_kernel<<<(Nn * Pp / 64) * (Dd / 64), 256>>>(bo, out);
}

// round 6
// speedup vs baseline: 3.3157x; 1.2267x over previous
#include <cuda_runtime.h>
#include <cuda_fp16.h>
#include <cstdint>

#define Nn 4
#define Pp 2048
#define Dd 512
#define Hh 8
#define HD 64
// sqrt(1/sqrt(512) * log2(e)) — folded into both q and k so QK^T lands in log2 domain
#define SQS 0.25250490f

// ---- scratch (__device__ globals; no allocations allowed) ----
__device__ __half g_qhi[Nn * Hh * Pp * HD];
__device__ __half g_qlo[Nn * Hh * Pp * HD];
__device__ __half g_khi[Nn * Hh * Pp * HD];
__device__ __half g_klo[Nn * Hh * Pp * HD];
__device__ __half g_vhi[Nn * Hh * Pp * HD];
__device__ __half g_vlo[Nn * Hh * Pp * HD];
__device__ __half g_E[(size_t)Nn * Hh * Pp * Pp];   // unnormalized exp, fp16
__device__ __half g_ohhi[Nn * Pp * Dd];
__device__ __half g_ohlo[Nn * Pp * Dd];
__device__ __half g_woThi[Dd * Dd];
__device__ __half g_woTlo[Dd * Dd];
__device__ float g_inv[Nn * Hh * Pp];

// ---- helpers ----
static __device__ __forceinline__ uint32_t s2u(const void* p) {
    uint32_t a;
    asm("{ .reg .u64 t; cvta.to.shared.u64 t, %1; cvt.u32.u64 %0, t; }" : "=r"(a) : "l"(p));
    return a;
}
static __device__ __forceinline__ void ldsm4(uint32_t* r, uint32_t a) {
    asm volatile("ldmatrix.sync.aligned.m8n8.x4.shared.b16 {%0,%1,%2,%3}, [%4];"
                 : "=r"(r[0]), "=r"(r[1]), "=r"(r[2]), "=r"(r[3]) : "r"(a));
}
static __device__ __forceinline__ void ldsm4t(uint32_t* r, uint32_t a) {
    asm volatile("ldmatrix.sync.aligned.m8n8.x4.trans.shared.b16 {%0,%1,%2,%3}, [%4];"
                 : "=r"(r[0]), "=r"(r[1]), "=r"(r[2]), "=r"(r[3]) : "r"(a));
}
static __device__ __forceinline__ void mma16816(float* c, const uint32_t* a,
                                                uint32_t b0, uint32_t b1) {
    asm volatile(
        "mma.sync.aligned.m16n8k16.row.col.f32.f16.f16.f32 "
        "{%0,%1,%2,%3}, {%4,%5,%6,%7}, {%8,%9}, {%0,%1,%2,%3};"
        : "+f"(c[0]), "+f"(c[1]), "+f"(c[2]), "+f"(c[3])
        : "r"(a[0]), "r"(a[1]), "r"(a[2]), "r"(a[3]), "r"(b0), "r"(b1));
}
// 2^t via MUFU
static __device__ __forceinline__ float ex2m(float t) {
    float r;
    asm("ex2.approx.f32 %0, %1;" : "=f"(r) : "f"(t));
    return r;
}
// 2^t via fp32 poly (FMA pipe). |t| < ~16. rel err ~4e-5.
static __device__ __forceinline__ float ex2p(float t) {
    const float MAGIC = 12582912.0f; // 1.5 * 2^23
    float r = __fadd_rn(t, MAGIC);
    float f = __fsub_rn(t, __fsub_rn(r, MAGIC)); // t - round(t), in [-0.5, 0.5]
    float p = fmaf(f, fmaf(f, fmaf(f, fmaf(f, 0.00961813f, 0.05550411f),
                                   0.24022651f), 0.69314718f), 1.0f);
    return __int_as_float(__float_as_int(p) + (__float_as_int(r) << 23));
}

// ---- Kernel 1: QKV projection -> fp16 hi/lo splits (q,k prescaled) -----
__global__ void qkv_kernel(const float* __restrict__ x,
                           const float* __restrict__ Wq,
                           const float* __restrict__ Wk,
                           const float* __restrict__ Wv) {
    extern __shared__ float sq[];
    float* wq_s = sq;
    float* wk_s = wq_s + 64 * 65;
    float* wv_s = wk_s + 64 * 65;
    float* xs   = wv_s + 64 * 65;

    int t = threadIdx.x;
    for (int idx = t; idx < 4096; idx += 256) {
        int e = idx >> 6, d = idx & 63;
        wq_s[e * 65 + d] = Wq[idx];
        wk_s[e * 65 + d] = Wk[idx];
        wv_s[e * 65 + d] = Wv[idx];
    }
    size_t R0 = (size_t)blockIdx.x * 32;
    const float4* xg = (const float4*)(x + R0 * 64);
    float4* xs4 = (float4*)xs;
    xs4[t]       = xg[t];
    xs4[t + 256] = xg[t + 256];
    __syncthreads();

    int w = t >> 5, l = t & 31;
    float aq[4][2] = {}, ak[4][2] = {}, av[4][2] = {};
#pragma unroll 4
    for (int d = 0; d < 64; d++) {
        float xv[4];
#pragma unroll
        for (int i = 0; i < 4; i++) xv[i] = xs[(w * 4 + i) * 64 + d];
        float q0 = wq_s[l * 65 + d], q1 = wq_s[(l + 32) * 65 + d];
        float k0 = wk_s[l * 65 + d], k1 = wk_s[(l + 32) * 65 + d];
        float v0 = wv_s[l * 65 + d], v1 = wv_s[(l + 32) * 65 + d];
#pragma unroll
        for (int i = 0; i < 4; i++) {
            aq[i][0] += xv[i] * q0; aq[i][1] += xv[i] * q1;
            ak[i][0] += xv[i] * k0; ak[i][1] += xv[i] * k1;
            av[i][0] += xv[i] * v0; av[i][1] += xv[i] * v1;
        }
    }
#pragma unroll
    for (int i = 0; i < 4; i++) {
        int R = (int)R0 + w * 4 + i;
        int n = R / (Pp * Hh);
        int rem = R % (Pp * Hh);
        int p = rem / Hh, h = rem % Hh;
        size_t base = ((size_t)(n * Hh + h) * Pp + p) * HD;
#pragma unroll
        for (int c = 0; c < 2; c++) {
            size_t ix = base + l + c * 32;
            float vq = aq[i][c] * SQS;
            float vk = ak[i][c] * SQS;
            float vv = av[i][c];
            __half hq = __float2half_rn(vq);
            __half hk = __float2half_rn(vk);
            __half hv = __float2half_rn(vv);
            g_qhi[ix] = hq; g_qlo[ix] = __float2half_rn(vq - __half2float(hq));
            g_khi[ix] = hk; g_klo[ix] = __float2half_rn(vk - __half2float(hk));
            g_vhi[ix] = hv; g_vlo[ix] = __float2half_rn(vv - __half2float(hv));
        }
    }
}

// ---- Kernel 2: fused HMMA attention ------------------------------------
// CTA = 64 q-rows of one (n,h). 128 threads = 4 warps, warp m = 16.
// smem rows padded to 72 halves (144B) -> conflict-free STS + ldmatrix.
#define SROW 72

__global__ void __launch_bounds__(128, 3) attn_hmma_kernel() {
    extern __shared__ __half sh[];
    __half* sKhi = sh;
    __half* sKlo = sh + 128 * SROW;
    __half* sVhi = sh + 2 * 128 * SROW;
    __half* sVlo = sh + 3 * 128 * SROW;
    uint32_t bKhi = s2u(sKhi), bKlo = s2u(sKlo), bVhi = s2u(sVhi), bVlo = s2u(sVlo);

    int t = threadIdx.x;
    int w = t >> 5, l = t & 31;
    int bx = blockIdx.x;
    int qt = bx & 31, h = (bx >> 5) & 7, n = bx >> 8;
    int nh = n * Hh + h;
    int q0 = qt * 64;

    int g = l >> 2, tq = l & 3;

    // ---- stage Q tile (64 rows) into K smem area, build A-frags ----
    {
        const __half* qh = g_qhi + ((size_t)nh * Pp + q0) * HD;
        const __half* ql = g_qlo + ((size_t)nh * Pp + q0) * HD;
#pragma unroll
        for (int i = 0; i < 4; i++) {
            int idx = t + i * 128;
            int row = idx >> 3, cg = idx & 7;
            *(uint4*)(sKhi + row * SROW + cg * 8) = *(const uint4*)(qh + row * 64 + cg * 8);
            *(uint4*)(sKlo + row * SROW + cg * 8) = *(const uint4*)(ql + row * 64 + cg * 8);
        }
    }
    __syncthreads();
    uint32_t qfh[4][4], qfl[4][4];
    {
        int arow = w * 16 + (l & 7) + ((l >> 3) & 1) * 8;
        int acol = (l >> 4) * 8;
#pragma unroll
        for (int s = 0; s < 4; s++) {
            uint32_t off = (uint32_t)((arow * SROW + s * 16 + acol) * 2);
            ldsm4(qfh[s], bKhi + off);
            ldsm4(qfl[s], bKlo + off);
        }
    }
    __syncthreads();

    float dacc[8][4];
#pragma unroll
    for (int i = 0; i < 8; i++)
#pragma unroll
        for (int j = 0; j < 4; j++) dacc[i][j] = 0.0f;
    float rs0 = 0.0f, rs1 = 0.0f;

    const __half* kgh = g_khi + (size_t)nh * Pp * HD;
    const __half* kgl = g_klo + (size_t)nh * Pp * HD;
    const __half* vgh = g_vhi + (size_t)nh * Pp * HD;
    const __half* vgl = g_vlo + (size_t)nh * Pp * HD;

    int rowE0 = q0 + w * 16 + g;
    __half* eslab = g_E + (size_t)nh * Pp * (size_t)Pp;

    for (int c = 0; c < 16; c++) {
        int c0 = c * 128;
        // load K,V chunk (hi/lo) into smem
#pragma unroll
        for (int i = 0; i < 8; i++) {
            int idx = t + i * 128;
            int row = idx >> 3, cg = idx & 7;
            size_t go = (size_t)(c0 + row) * 64 + cg * 8;
            int so = row * SROW + cg * 8;
            *(uint4*)(sKhi + so) = *(const uint4*)(kgh + go);
            *(uint4*)(sKlo + so) = *(const uint4*)(kgl + go);
            *(uint4*)(sVhi + so) = *(const uint4*)(vgh + go);
            *(uint4*)(sVlo + so) = *(const uint4*)(vgl + go);
        }
        __syncthreads();

#pragma unroll
        for (int nhf = 0; nhf < 2; nhf++) {
            // ---- QK^T for 64 kv cols ----
            float cc[8][4];
#pragma unroll
            for (int i = 0; i < 8; i++)
#pragma unroll
                for (int j2 = 0; j2 < 4; j2++) cc[i][j2] = 0.0f;

#pragma unroll
            for (int j = 0; j < 8; j++) {
                int lrow = nhf * 64 + j * 8 + (l & 7);
                int lcol = ((l >> 3) & 3) * 8;
                uint32_t off = (uint32_t)((lrow * SROW + lcol) * 2);
                uint32_t kh[4], kh2[4], kl[4], kl2[4];
                ldsm4(kh, bKhi + off);
                ldsm4(kh2, bKhi + off + 64);
                ldsm4(kl, bKlo + off);
                ldsm4(kl2, bKlo + off + 64);
#pragma unroll
                for (int s = 0; s < 4; s++) {
                    uint32_t bh0 = (s < 2) ? kh[(s & 1) * 2]     : kh2[(s & 1) * 2];
                    uint32_t bh1 = (s < 2) ? kh[(s & 1) * 2 + 1] : kh2[(s & 1) * 2 + 1];
                    uint32_t bl0 = (s < 2) ? kl[(s & 1) * 2]     : kl2[(s & 1) * 2];
                    uint32_t bl1 = (s < 2) ? kl[(s & 1) * 2 + 1] : kl2[(s & 1) * 2 + 1];
                    mma16816(cc[j], qfh[s], bh0, bh1);
                    mma16816(cc[j], qfh[s], bl0, bl1);
                    mma16816(cc[j], qfl[s], bh0, bh1);
                }
            }

            // ---- exp epilogue: fp16 E store + P frags (same values) ----
            uint32_t phi_[4][4], plo_[4][4];
#pragma unroll
            for (int j = 0; j < 8; j++) {
                float v0 = ex2m(cc[j][0]);
                float v1 = ex2m(cc[j][1]);
                float v2 = (j & 1) ? ex2p(cc[j][2]) : ex2m(cc[j][2]);
                float v3 = ex2p(cc[j][3]);
                rs0 += v0 + v1;
                rs1 += v2 + v3;
                __half2 h01 = __floats2half2_rn(v0, v1);
                __half2 h23 = __floats2half2_rn(v2, v3);
                int col = c0 + nhf * 64 + j * 8 + 2 * tq;
                *(__half2*)(eslab + (size_t)rowE0 * Pp + col)       = h01;
                *(__half2*)(eslab + (size_t)(rowE0 + 8) * Pp + col) = h23;
                float2 f01 = __half22float2(h01);
                float2 f23 = __half22float2(h23);
                __half2 l01 = __floats2half2_rn(v0 - f01.x, v1 - f01.y);
                __half2 l23 = __floats2half2_rn(v2 - f23.x, v3 - f23.y);
                int s = j >> 1, rp = (j & 1) * 2;
                phi_[s][rp]     = *(uint32_t*)&h01;
                phi_[s][rp + 1] = *(uint32_t*)&h23;
                plo_[s][rp]     = *(uint32_t*)&l01;
                plo_[s][rp + 1] = *(uint32_t*)&l23;
            }

            // ---- AV accumulate ----
#pragma unroll
            for (int s = 0; s < 4; s++) {
                int lrow = nhf * 64 + s * 16 + (l & 7) + ((l >> 3) & 1) * 8;
#pragma unroll
                for (int djp = 0; djp < 4; djp++) {
                    int dj = djp * 2;
                    int lcol = dj * 8 + (l >> 4) * 8;
                    uint32_t off = (uint32_t)((lrow * SROW + lcol) * 2);
                    uint32_t vh[4], vl[4];
                    ldsm4t(vh, bVhi + off);
                    ldsm4t(vl, bVlo + off);
                    mma16816(dacc[dj], phi_[s], vh[0], vh[1]);
                    mma16816(dacc[dj], phi_[s], vl[0], vl[1]);
                    mma16816(dacc[dj], plo_[s], vh[0], vh[1]);
                    mma16816(dacc[dj + 1], phi_[s], vh[2], vh[3]);
                    mma16816(dacc[dj + 1], phi_[s], vl[2], vl[3]);
                    mma16816(dacc[dj + 1], plo_[s], vh[2], vh[3]);
                }
            }
        }
        __syncthreads();
    }

    // ---- finalize: rowsums, inv, oh hi/lo store ----
    rs0 += __shfl_xor_sync(0xffffffffu, rs0, 1);
    rs0 += __shfl_xor_sync(0xffffffffu, rs0, 2);
    rs1 += __shfl_xor_sync(0xffffffffu, rs1, 1);
    rs1 += __shfl_xor_sync(0xffffffffu, rs1, 2);
    float inv0 = 1.0f / rs0, inv1 = 1.0f / rs1;
    if (tq == 0) {
        g_inv[nh * Pp + rowE0]     = inv0;
        g_inv[nh * Pp + rowE0 + 8] = inv1;
    }
    size_t ob0 = ((size_t)n * Pp + rowE0) * Dd + h * HD;
    size_t ob1 = ((size_t)n * Pp + rowE0 + 8) * Dd + h * HD;
#pragma unroll
    for (int dj = 0; dj < 8; dj++) {
        int cold = dj * 8 + 2 * tq;
        float a0 = dacc[dj][0] * inv0, a1 = dacc[dj][1] * inv0;
        float a2 = dacc[dj][2] * inv1, a3 = dacc[dj][3] * inv1;
        __half2 h0 = __floats2half2_rn(a0, a1);
        __half2 h1 = __floats2half2_rn(a2, a3);
        float2 f0 = __half22float2(h0);
        float2 f1 = __half22float2(h1);
        __half2 l0 = __floats2half2_rn(a0 - f0.x, a1 - f0.y);
        __half2 l1 = __floats2half2_rn(a2 - f1.x, a3 - f1.y);
        *(__half2*)(g_ohhi + ob0 + cold) = h0;
        *(__half2*)(g_ohlo + ob0 + cold) = l0;
        *(__half2*)(g_ohhi + ob1 + cold) = h1;
        *(__half2*)(g_ohlo + ob1 + cold) = l1;
    }
}

// ---- Kernel 3: normalize fp16 E -> fp32 attention ----------------------
__global__ void norm_kernel(float* __restrict__ attn) {
    size_t i = ((size_t)blockIdx.x * 256 + threadIdx.x) * 8;
    float inv = g_inv[i >> 11];
    uint4 hraw = *(const uint4*)(g_E + i);
    __half2* hp = (__half2*)&hraw;
    float4 o0, o1;
    float2 f;
    f = __half22float2(hp[0]); o0.x = f.x * inv; o0.y = f.y * inv;
    f = __half22float2(hp[1]); o0.z = f.x * inv; o0.w = f.y * inv;
    f = __half22float2(hp[2]); o1.x = f.x * inv; o1.y = f.y * inv;
    f = __half22float2(hp[3]); o1.z = f.x * inv; o1.w = f.y * inv;
    *(float4*)(attn + i)     = o0;
    *(float4*)(attn + i + 4) = o1;
}

// ---- Kernel 4a: Wo transpose -> fp16 hi/lo splits ----------------------
__global__ void woT_kernel(const float* __restrict__ Wo) {
    __shared__ float tile[32][33];
    int x0 = blockIdx.x * 32, y0 = blockIdx.y * 32;
    int tx = threadIdx.x, ty = threadIdx.y;
#pragma unroll
    for (int i = 0; i < 32; i += 8)
        tile[ty + i][tx] = Wo[(size_t)(y0 + ty + i) * Dd + x0 + tx];
    __syncthreads();
#pragma unroll
    for (int i = 0; i < 32; i += 8) {
        float v = tile[tx][ty + i];
        __half hv = __float2half_rn(v);
        size_t ix = (size_t)(x0 + ty + i) * Dd + y0 + tx;
        g_woThi[ix] = hv;
        g_woTlo[ix] = __float2half_rn(v - __half2float(hv));
    }
}

// ---- Kernel 4b: out = oh @ Wo^T + bo (HMMA, hi/lo split) ---------------
__global__ void __launch_bounds__(128) out_kernel(const float* __restrict__ bo,
                                                  float* __restrict__ out) {
    __shared__ __half sA[2][64 * SROW];
    __shared__ __half sB[2][64 * SROW];
    uint32_t bAhi = s2u(sA[0]), bAlo = s2u(sA[1]);
    uint32_t bBhi = s2u(sB[0]), bBlo = s2u(sB[1]);

    int t = threadIdx.x;
    int w = t >> 5, l = t & 31;
    int ct = blockIdx.x & 7;
    int rt = blockIdx.x >> 3;
    int r0 = rt * 64, e0 = ct * 64;

    float dacc[8][4];
#pragma unroll
    for (int i = 0; i < 8; i++)
#pragma unroll
        for (int j = 0; j < 4; j++) dacc[i][j] = 0.0f;

    for (int kc = 0; kc < Dd; kc += 64) {
        __syncthreads();
#pragma unroll
        for (int i = 0; i < 4; i++) {
            int idx = t + i * 128;
            int row = idx >> 3, cg = (idx & 7) * 8;
            size_t ga = (size_t)(r0 + row) * Dd + kc + cg;
            int so = row * SROW + cg;
            *(uint4*)(sA[0] + so) = *(const uint4*)(g_ohhi + ga);
            *(uint4*)(sA[1] + so) = *(const uint4*)(g_ohlo + ga);
            size_t gb = (size_t)(kc + row) * Dd + e0 + cg;
            *(uint4*)(sB[0] + so) = *(const uint4*)(g_woThi + gb);
            *(uint4*)(sB[1] + so) = *(const uint4*)(g_woTlo + gb);
        }
        __syncthreads();

        uint32_t afh[4][4], afl[4][4];
        int arow = w * 16 + (l & 7) + ((l >> 3) & 1) * 8;
        int acol = (l >> 4) * 8;
#pragma unroll
        for (int s = 0; s < 4; s++) {
            uint32_t off = (uint32_t)((arow * SROW + s * 16 + acol) * 2);
            ldsm4(afh[s], bAhi + off);
            ldsm4(afl[s], bAlo + off);
        }
#pragma unroll
        for (int s = 0; s < 4; s++) {
            int lrow = s * 16 + (l & 7) + ((l >> 3) & 1) * 8;
#pragma unroll
            for (int djp = 0; djp < 4; djp++) {
                int dj = djp * 2;
                int lcol = dj * 8 + (l >> 4) * 8;
                uint32_t off = (uint32_t)((lrow * SROW + lcol) * 2);
                uint32_t bh[4], bl[4];
                ldsm4t(bh, bBhi + off);
                ldsm4t(bl, bBlo + off);
                mma16816(dacc[dj], afh[s], bh[0], bh[1]);
                mma16816(dacc[dj], afh[s], bl[0], bl[1]);
                mma16816(dacc[dj], afl[s], bh[0], bh[1]);
                mma16816(dacc[dj + 1], afh[s], bh[2], bh[3]);
                mma16816(dacc[dj + 1], afh[s], bl[2], bl[3]);
                mma16816(dacc[dj + 1], afl[s], bh[2], bh[3]);
            }
        }
    }

    int g = l >> 2, tq = l & 3;
    int row0 = r0 + w * 16 + g, row1 = row0 + 8;
#pragma unroll
    for (int dj = 0; dj < 8; dj++) {
        int col = e0 + dj * 8 + 2 * tq;
        float2 bias = *(const float2*)(bo + col);
        *(float2*)(out + (size_t)row0 * Dd + col) =
            make_float2(dacc[dj][0] + bias.x, dacc[dj][1] + bias.y);
        *(float2*)(out + (size_t)row1 * Dd + col) =
            make_float2(dacc[dj][2] + bias.x, dacc[dj][3] + bias.y);
    }
}

extern "C" void kernel_launch(void* const* d_in, const int* in_sizes, int n_in,
                              void* d_out, int out_size) {
    const float* xyz = (const float*)d_in[0];
    const float* Wq  = (const float*)d_in[1];
    const float* Wk  = (const float*)d_in[2];
    const float* Wv  = (const float*)d_in[3];
    const float* Wo  = (const float*)d_in[4];
    const float* bo  = (const float*)d_in[5];
    float* out  = (float*)d_out;                          // (4,2048,512)
    float* attn = (float*)d_out + (size_t)Nn * Pp * Dd;   // (4,8,2048,2048)

    static const int QKV_SMEM  = (3 * 64 * 65 + 32 * 64) * 4;
    static const int ATTN_SMEM = 4 * 128 * SROW * 2;      // 73728 B
    cudaFuncSetAttribute(qkv_kernel, cudaFuncAttributeMaxDynamicSharedMemorySize, QKV_SMEM);
    cudaFuncSetAttribute(attn_hmma_kernel, cudaFuncAttributeMaxDynamicSharedMemorySize, ATTN_SMEM);

    woT_kernel<<<dim3(16, 16), dim3(32, 8)>>>(Wo);
    qkv_kernel<<<(Nn * Pp * Hh) / 32, 256, QKV_SMEM>>>(xyz, Wq, Wk, Wv);
    attn_hmma_kernel<<<Nn * Hh * (Pp / 64), 128, ATTN_SMEM>>>();
    norm_kernel<<<(int)(((size_t)Nn * Hh * Pp * Pp) / 8 / 256), 256>>>(attn);
    out_kernel<<<(Nn * Pp / 64) * (Dd / 64), 128>>>(bo, out);
}

// round 9
// speedup vs baseline: 4.9566x; 1.4949x over previous
#include <cuda_runtime.h>
#include <cuda_fp16.h>
#include <cstdint>

#define Nn 4
#define Pp 2048
#define Dd 512
#define Hh 8
#define HD 64
// sqrt(1/sqrt(512) * log2(e)) — folded into both q and k so QK^T lands in log2 domain
#define SQS 0.25250490f

// ---- scratch (__device__ globals; no allocations allowed) ----
__device__ __half g_q[Nn * Hh * Pp * HD];
__device__ __half g_k[Nn * Hh * Pp * HD];
__device__ __half g_v[Nn * Hh * Pp * HD];
__device__ __half g_E[(size_t)Nn * Hh * Pp * Pp];   // unnormalized exp, fp16
__device__ __half g_oh[Nn * Pp * Dd];
__device__ __half g_woT[Dd * Dd];
__device__ float g_inv[Nn * Hh * Pp];

// ---- helpers ----
static __device__ __forceinline__ uint32_t s2u(const void* p) {
    uint32_t a;
    asm("{ .reg .u64 t; cvta.to.shared.u64 t, %1; cvt.u32.u64 %0, t; }" : "=r"(a) : "l"(p));
    return a;
}
static __device__ __forceinline__ void ldsm4(uint32_t* r, uint32_t a) {
    asm volatile("ldmatrix.sync.aligned.m8n8.x4.shared.b16 {%0,%1,%2,%3}, [%4];"
                 : "=r"(r[0]), "=r"(r[1]), "=r"(r[2]), "=r"(r[3]) : "r"(a));
}
static __device__ __forceinline__ void ldsm4t(uint32_t* r, uint32_t a) {
    asm volatile("ldmatrix.sync.aligned.m8n8.x4.trans.shared.b16 {%0,%1,%2,%3}, [%4];"
                 : "=r"(r[0]), "=r"(r[1]), "=r"(r[2]), "=r"(r[3]) : "r"(a));
}
static __device__ __forceinline__ void mma16816(float* c, const uint32_t* a,
                                                uint32_t b0, uint32_t b1) {
    asm volatile(
        "mma.sync.aligned.m16n8k16.row.col.f32.f16.f16.f32 "
        "{%0,%1,%2,%3}, {%4,%5,%6,%7}, {%8,%9}, {%0,%1,%2,%3};"
        : "+f"(c[0]), "+f"(c[1]), "+f"(c[2]), "+f"(c[3])
        : "r"(a[0]), "r"(a[1]), "r"(a[2]), "r"(a[3]), "r"(b0), "r"(b1));
}
// 2^t via MUFU
static __device__ __forceinline__ float ex2m(float t) {
    float r;
    asm("ex2.approx.f32 %0, %1;" : "=f"(r) : "f"(t));
    return r;
}

// ---- Kernel 1: QKV projection -> fp16 (q,k prescaled into log2 domain) --
__global__ void qkv_kernel(const float* __restrict__ x,
                           const float* __restrict__ Wq,
                           const float* __restrict__ Wk,
                           const float* __restrict__ Wv) {
    extern __shared__ float sq[];
    float* wq_s = sq;
    float* wk_s = wq_s + 64 * 65;
    float* wv_s = wk_s + 64 * 65;
    float* xs   = wv_s + 64 * 65;

    int t = threadIdx.x;
    for (int idx = t; idx < 4096; idx += 256) {
        int e = idx >> 6, d = idx & 63;
        wq_s[e * 65 + d] = Wq[idx];
        wk_s[e * 65 + d] = Wk[idx];
        wv_s[e * 65 + d] = Wv[idx];
    }
    size_t R0 = (size_t)blockIdx.x * 32;
    const float4* xg = (const float4*)(x + R0 * 64);
    float4* xs4 = (float4*)xs;
    xs4[t]       = xg[t];
    xs4[t + 256] = xg[t + 256];
    __syncthreads();

    int w = t >> 5, l = t & 31;
    float aq[4][2] = {}, ak[4][2] = {}, av[4][2] = {};
#pragma unroll 4
    for (int d = 0; d < 64; d++) {
        float xv[4];
#pragma unroll
        for (int i = 0; i < 4; i++) xv[i] = xs[(w * 4 + i) * 64 + d];
        float q0 = wq_s[l * 65 + d], q1 = wq_s[(l + 32) * 65 + d];
        float k0 = wk_s[l * 65 + d], k1 = wk_s[(l + 32) * 65 + d];
        float v0 = wv_s[l * 65 + d], v1 = wv_s[(l + 32) * 65 + d];
#pragma unroll
        for (int i = 0; i < 4; i++) {
            aq[i][0] += xv[i] * q0; aq[i][1] += xv[i] * q1;
            ak[i][0] += xv[i] * k0; ak[i][1] += xv[i] * k1;
            av[i][0] += xv[i] * v0; av[i][1] += xv[i] * v1;
        }
    }
#pragma unroll
    for (int i = 0; i < 4; i++) {
        int R = (int)R0 + w * 4 + i;
        int n = R / (Pp * Hh);
        int rem = R % (Pp * Hh);
        int p = rem / Hh, h = rem % Hh;
        size_t base = ((size_t)(n * Hh + h) * Pp + p) * HD;
#pragma unroll
        for (int c = 0; c < 2; c++) {
            size_t ix = base + l + c * 32;
            g_q[ix] = __float2half_rn(aq[i][c] * SQS);
            g_k[ix] = __float2half_rn(ak[i][c] * SQS);
            g_v[ix] = __float2half_rn(av[i][c]);
        }
    }
}

// ---- Kernel 2: fused HMMA attention (pure fp16 operands) ---------------
// CTA = 64 q-rows of one (n,h). 128 threads = 4 warps, warp m = 16.
// smem rows padded to 72 halves (144B) -> conflict-free STS + ldmatrix.
#define SROW 72

__global__ void __launch_bounds__(128, 3) attn_hmma_kernel() {
    extern __shared__ __half sh[];
    __half* sK = sh;
    __half* sV = sh + 128 * SROW;
    uint32_t bK = s2u(sK), bV = s2u(sV);

    int t = threadIdx.x;
    int w = t >> 5, l = t & 31;
    int bx = blockIdx.x;
    int qt = bx & 31, h = (bx >> 5) & 7, n = bx >> 8;
    int nh = n * Hh + h;
    int q0 = qt * 64;

    int g = l >> 2, tq = l & 3;

    // ---- stage Q tile (64 rows) into K smem area, build A-frags ----
    {
        const __half* qh = g_q + ((size_t)nh * Pp + q0) * HD;
#pragma unroll
        for (int i = 0; i < 4; i++) {
            int idx = t + i * 128;
            int row = idx >> 3, cg = idx & 7;
            *(uint4*)(sK + row * SROW + cg * 8) = *(const uint4*)(qh + row * 64 + cg * 8);
        }
    }
    __syncthreads();
    uint32_t qf[4][4];
    {
        int arow = w * 16 + (l & 7) + ((l >> 3) & 1) * 8;
        int acol = (l >> 4) * 8;
#pragma unroll
        for (int s = 0; s < 4; s++) {
            uint32_t off = (uint32_t)((arow * SROW + s * 16 + acol) * 2);
            ldsm4(qf[s], bK + off);
        }
    }
    __syncthreads();

    float dacc[8][4];
#pragma unroll
    for (int i = 0; i < 8; i++)
#pragma unroll
        for (int j = 0; j < 4; j++) dacc[i][j] = 0.0f;
    float rs0 = 0.0f, rs1 = 0.0f;

    const __half* kg = g_k + (size_t)nh * Pp * HD;
    const __half* vg = g_v + (size_t)nh * Pp * HD;

    int rowE0 = q0 + w * 16 + g;
    __half* eslab = g_E + (size_t)nh * Pp * (size_t)Pp;

    for (int c = 0; c < 16; c++) {
        int c0 = c * 128;
        // load K,V chunk into smem
#pragma unroll
        for (int i = 0; i < 8; i++) {
            int idx = t + i * 128;
            int row = idx >> 3, cg = idx & 7;
            size_t go = (size_t)(c0 + row) * 64 + cg * 8;
            int so = row * SROW + cg * 8;
            *(uint4*)(sK + so) = *(const uint4*)(kg + go);
            *(uint4*)(sV + so) = *(const uint4*)(vg + go);
        }
        __syncthreads();

#pragma unroll
        for (int nhf = 0; nhf < 2; nhf++) {
            // ---- QK^T for 64 kv cols ----
            float cc[8][4];
#pragma unroll
            for (int i = 0; i < 8; i++)
#pragma unroll
                for (int j2 = 0; j2 < 4; j2++) cc[i][j2] = 0.0f;

#pragma unroll
            for (int j = 0; j < 8; j++) {
                int lrow = nhf * 64 + j * 8 + (l & 7);
                int lcol = ((l >> 3) & 3) * 8;
                uint32_t off = (uint32_t)((lrow * SROW + lcol) * 2);
                uint32_t kh[4], kh2[4];
                ldsm4(kh, bK + off);
                ldsm4(kh2, bK + off + 64);
#pragma unroll
                for (int s = 0; s < 4; s++) {
                    uint32_t b0 = (s < 2) ? kh[(s & 1) * 2]     : kh2[(s & 1) * 2];
                    uint32_t b1 = (s < 2) ? kh[(s & 1) * 2 + 1] : kh2[(s & 1) * 2 + 1];
                    mma16816(cc[j], qf[s], b0, b1);
                }
            }

            // ---- exp epilogue: fp16 E store + P frags ----
            uint32_t pf[4][4];
#pragma unroll
            for (int j = 0; j < 8; j++) {
                float v0 = ex2m(cc[j][0]);
                float v1 = ex2m(cc[j][1]);
                float v2 = ex2m(cc[j][2]);
                float v3 = ex2m(cc[j][3]);
                rs0 += v0 + v1;
                rs1 += v2 + v3;
                __half2 h01 = __floats2half2_rn(v0, v1);
                __half2 h23 = __floats2half2_rn(v2, v3);
                int col = c0 + nhf * 64 + j * 8 + 2 * tq;
                *(__half2*)(eslab + (size_t)rowE0 * Pp + col)       = h01;
                *(__half2*)(eslab + (size_t)(rowE0 + 8) * Pp + col) = h23;
                int s = j >> 1, rp = (j & 1) * 2;
                pf[s][rp]     = *(uint32_t*)&h01;
                pf[s][rp + 1] = *(uint32_t*)&h23;
            }

            // ---- AV accumulate (P fp16 x V fp16) ----
#pragma unroll
            for (int s = 0; s < 4; s++) {
                int lrow = nhf * 64 + s * 16 + (l & 7) + ((l >> 3) & 1) * 8;
#pragma unroll
                for (int djp = 0; djp < 4; djp++) {
                    int dj = djp * 2;
                    int lcol = dj * 8 + (l >> 4) * 8;
                    uint32_t off = (uint32_t)((lrow * SROW + lcol) * 2);
                    uint32_t vh[4];
                    ldsm4t(vh, bV + off);
                    mma16816(dacc[dj],     pf[s], vh[0], vh[1]);
                    mma16816(dacc[dj + 1], pf[s], vh[2], vh[3]);
                }
            }
        }
        __syncthreads();
    }

    // ---- finalize: rowsums, inv, oh fp16 store ----
    rs0 += __shfl_xor_sync(0xffffffffu, rs0, 1);
    rs0 += __shfl_xor_sync(0xffffffffu, rs0, 2);
    rs1 += __shfl_xor_sync(0xffffffffu, rs1, 1);
    rs1 += __shfl_xor_sync(0xffffffffu, rs1, 2);
    float inv0 = 1.0f / rs0, inv1 = 1.0f / rs1;
    if (tq == 0) {
        g_inv[nh * Pp + rowE0]     = inv0;
        g_inv[nh * Pp + rowE0 + 8] = inv1;
    }
    size_t ob0 = ((size_t)n * Pp + rowE0) * Dd + h * HD;
    size_t ob1 = ((size_t)n * Pp + rowE0 + 8) * Dd + h * HD;
#pragma unroll
    for (int dj = 0; dj < 8; dj++) {
        int cold = dj * 8 + 2 * tq;
        *(__half2*)(g_oh + ob0 + cold) =
            __floats2half2_rn(dacc[dj][0] * inv0, dacc[dj][1] * inv0);
        *(__half2*)(g_oh + ob1 + cold) =
            __floats2half2_rn(dacc[dj][2] * inv1, dacc[dj][3] * inv1);
    }
}

// ---- Kernel 3: normalize fp16 E -> fp32 attention (streaming) ----------
__global__ void norm_kernel(float* __restrict__ attn) {
    size_t i = ((size_t)blockIdx.x * 256 + threadIdx.x) * 8;
    float inv = g_inv[i >> 11];
    uint4 hraw = __ldcs((const uint4*)(g_E + i));
    __half2* hp = (__half2*)&hraw;
    float4 o0, o1;
    float2 f;
    f = __half22float2(hp[0]); o0.x = f.x * inv; o0.y = f.y * inv;
    f = __half22float2(hp[1]); o0.z = f.x * inv; o0.w = f.y * inv;
    f = __half22float2(hp[2]); o1.x = f.x * inv; o1.y = f.y * inv;
    f = __half22float2(hp[3]); o1.z = f.x * inv; o1.w = f.y * inv;
    __stcs((float4*)(attn + i), o0);
    __stcs((float4*)(attn + i + 4), o1);
}

// ---- Kernel 4a: Wo transpose -> fp16 -----------------------------------
__global__ void woT_kernel(const float* __restrict__ Wo) {
    __shared__ float tile[32][33];
    int x0 = blockIdx.x * 32, y0 = blockIdx.y * 32;
    int tx = threadIdx.x, ty = threadIdx.y;
#pragma unroll
    for (int i = 0; i < 32; i += 8)
        tile[ty + i][tx] = Wo[(size_t)(y0 + ty + i) * Dd + x0 + tx];
    __syncthreads();
#pragma unroll
    for (int i = 0; i < 32; i += 8)
        g_woT[(size_t)(x0 + ty + i) * Dd + y0 + tx] = __float2half_rn(tile[tx][ty + i]);
}

// ---- Kernel 4b: out = oh @ Wo^T + bo (fp16 HMMA) -----------------------
__global__ void __launch_bounds__(128) out_kernel(const float* __restrict__ bo,
                                                  float* __restrict__ out) {
    __shared__ __half sA[64 * SROW];
    __shared__ __half sB[64 * SROW];
    uint32_t bA = s2u(sA), bB = s2u(sB);

    int t = threadIdx.x;
    int w = t >> 5, l = t & 31;
    int ct = blockIdx.x & 7;
    int rt = blockIdx.x >> 3;
    int r0 = rt * 64, e0 = ct * 64;

    float dacc[8][4];
#pragma unroll
    for (int i = 0; i < 8; i++)
#pragma unroll
        for (int j = 0; j < 4; j++) dacc[i][j] = 0.0f;

    for (int kc = 0; kc < Dd; kc += 64) {
        __syncthreads();
#pragma unroll
        for (int i = 0; i < 4; i++) {
            int idx = t + i * 128;
            int row = idx >> 3, cg = (idx & 7) * 8;
            int so = row * SROW + cg;
            *(uint4*)(sA + so) = *(const uint4*)(g_oh + (size_t)(r0 + row) * Dd + kc + cg);
            *(uint4*)(sB + so) = *(const uint4*)(g_woT + (size_t)(kc + row) * Dd + e0 + cg);
        }
        __syncthreads();

        uint32_t af[4][4];
        int arow = w * 16 + (l & 7) + ((l >> 3) & 1) * 8;
        int acol = (l >> 4) * 8;
#pragma unroll
        for (int s = 0; s < 4; s++) {
            uint32_t off = (uint32_t)((arow * SROW + s * 16 + acol) * 2);
            ldsm4(af[s], bA + off);
        }
#pragma unroll
        for (int s = 0; s < 4; s++) {
            int lrow = s * 16 + (l & 7) + ((l >> 3) & 1) * 8;
#pragma unroll
            for (int djp = 0; djp < 4; djp++) {
                int dj = djp * 2;
                int lcol = dj * 8 + (l >> 4) * 8;
                uint32_t off = (uint32_t)((lrow * SROW + lcol) * 2);
                uint32_t bh[4];
                ldsm4t(bh, bB + off);
                mma16816(dacc[dj],     af[s], bh[0], bh[1]);
                mma16816(dacc[dj + 1], af[s], bh[2], bh[3]);
            }
        }
    }

    int g = l >> 2, tq = l & 3;
    int row0 = r0 + w * 16 + g, row1 = row0 + 8;
#pragma unroll
    for (int dj = 0; dj < 8; dj++) {
        int col = e0 + dj * 8 + 2 * tq;
        float2 bias = *(const float2*)(bo + col);
        *(float2*)(out + (size_t)row0 * Dd + col) =
            make_float2(dacc[dj][0] + bias.x, dacc[dj][1] + bias.y);
        *(float2*)(out + (size_t)row1 * Dd + col) =
            make_float2(dacc[dj][2] + bias.x, dacc[dj][3] + bias.y);
    }
}

extern "C" void kernel_launch(void* const* d_in, const int* in_sizes, int n_in,
                              void* d_out, int out_size) {
    const float* xyz = (const float*)d_in[0];
    const float* Wq  = (const float*)d_in[1];
    const float* Wk  = (const float*)d_in[2];
    const float* Wv  = (const float*)d_in[3];
    const float* Wo  = (const float*)d_in[4];
    const float* bo  = (const float*)d_in[5];
    float* out  = (float*)d_out;                          // (4,2048,512)
    float* attn = (float*)d_out + (size_t)Nn * Pp * Dd;   // (4,8,2048,2048)

    static const int QKV_SMEM  = (3 * 64 * 65 + 32 * 64) * 4;
    static const int ATTN_SMEM = 2 * 128 * SROW * 2;      // 36864 B
    cudaFuncSetAttribute(qkv_kernel, cudaFuncAttributeMaxDynamicSharedMemorySize, QKV_SMEM);
    cudaFuncSetAttribute(attn_hmma_kernel, cudaFuncAttributeMaxDynamicSharedMemorySize, ATTN_SMEM);

    woT_kernel<<<dim3(16, 16), dim3(32, 8)>>>(Wo);
    qkv_kernel<<<(Nn * Pp * Hh) / 32, 256, QKV_SMEM>>>(xyz, Wq, Wk, Wv);
    attn_hmma_kernel<<<Nn * Hh * (Pp / 64), 128, ATTN_SMEM>>>();
    norm_kernel<<<(int)(((size_t)Nn * Hh * Pp * Pp) / 8 / 256), 256>>>(attn);
    out_kernel<<<(Nn * Pp / 64) * (Dd / 64), 128>>>(bo, out);
}

// round 10
// speedup vs baseline: 5.2052x; 1.0502x over previous
#include <cuda_runtime.h>
#include <cuda_fp16.h>
#include <cstdint>

#define Nn 4
#define Pp 2048
#define Dd 512
#define Hh 8
#define HD 64
// sqrt(1/sqrt(512) * log2(e)) — folded into both q and k so QK^T lands in log2 domain
#define SQS 0.25250490f

// ---- scratch (__device__ globals; no allocations allowed) ----
__device__ __half g_q[Nn * Hh * Pp * HD];
__device__ __half g_k[Nn * Hh * Pp * HD];
__device__ __half g_v[Nn * Hh * Pp * HD];
__device__ __half g_E[(size_t)Nn * Hh * Pp * Pp];   // unnormalized exp, fp16
__device__ __half g_oh[Nn * Pp * Dd];
__device__ __half g_woT[Dd * Dd];
__device__ float g_inv[Nn * Hh * Pp];

// ---- helpers ----
static __device__ __forceinline__ uint32_t s2u(const void* p) {
    uint32_t a;
    asm("{ .reg .u64 t; cvta.to.shared.u64 t, %1; cvt.u32.u64 %0, t; }" : "=r"(a) : "l"(p));
    return a;
}
static __device__ __forceinline__ void ldsm4(uint32_t* r, uint32_t a) {
    asm volatile("ldmatrix.sync.aligned.m8n8.x4.shared.b16 {%0,%1,%2,%3}, [%4];"
                 : "=r"(r[0]), "=r"(r[1]), "=r"(r[2]), "=r"(r[3]) : "r"(a));
}
static __device__ __forceinline__ void ldsm4t(uint32_t* r, uint32_t a) {
    asm volatile("ldmatrix.sync.aligned.m8n8.x4.trans.shared.b16 {%0,%1,%2,%3}, [%4];"
                 : "=r"(r[0]), "=r"(r[1]), "=r"(r[2]), "=r"(r[3]) : "r"(a));
}
static __device__ __forceinline__ void mma16816(float* c, const uint32_t* a,
                                                uint32_t b0, uint32_t b1) {
    asm volatile(
        "mma.sync.aligned.m16n8k16.row.col.f32.f16.f16.f32 "
        "{%0,%1,%2,%3}, {%4,%5,%6,%7}, {%8,%9}, {%0,%1,%2,%3};"
        : "+f"(c[0]), "+f"(c[1]), "+f"(c[2]), "+f"(c[3])
        : "r"(a[0]), "r"(a[1]), "r"(a[2]), "r"(a[3]), "r"(b0), "r"(b1));
}
// 2^t via MUFU
static __device__ __forceinline__ float ex2m(float t) {
    float r;
    asm("ex2.approx.f32 %0, %1;" : "=f"(r) : "f"(t));
    return r;
}
static __device__ __forceinline__ void cpasync16(uint32_t s, const void* g) {
    asm volatile("cp.async.cg.shared.global [%0], [%1], 16;" :: "r"(s), "l"(g));
}
#define CP_COMMIT() asm volatile("cp.async.commit_group;" ::: "memory")
#define CP_WAIT0()  asm volatile("cp.async.wait_group 0;" ::: "memory")
#define CP_WAIT1()  asm volatile("cp.async.wait_group 1;" ::: "memory")

// ---- Kernel 1: QKV projection -> fp16 (q,k prescaled into log2 domain) --
__global__ void qkv_kernel(const float* __restrict__ x,
                           const float* __restrict__ Wq,
                           const float* __restrict__ Wk,
                           const float* __restrict__ Wv) {
    extern __shared__ float sq[];
    float* wq_s = sq;
    float* wk_s = wq_s + 64 * 65;
    float* wv_s = wk_s + 64 * 65;
    float* xs   = wv_s + 64 * 65;

    int t = threadIdx.x;
    for (int idx = t; idx < 4096; idx += 256) {
        int e = idx >> 6, d = idx & 63;
        wq_s[e * 65 + d] = Wq[idx];
        wk_s[e * 65 + d] = Wk[idx];
        wv_s[e * 65 + d] = Wv[idx];
    }
    size_t R0 = (size_t)blockIdx.x * 32;
    const float4* xg = (const float4*)(x + R0 * 64);
    float4* xs4 = (float4*)xs;
    xs4[t]       = xg[t];
    xs4[t + 256] = xg[t + 256];
    __syncthreads();

    int w = t >> 5, l = t & 31;
    float aq[4][2] = {}, ak[4][2] = {}, av[4][2] = {};
#pragma unroll 4
    for (int d = 0; d < 64; d++) {
        float xv[4];
#pragma unroll
        for (int i = 0; i < 4; i++) xv[i] = xs[(w * 4 + i) * 64 + d];
        float q0 = wq_s[l * 65 + d], q1 = wq_s[(l + 32) * 65 + d];
        float k0 = wk_s[l * 65 + d], k1 = wk_s[(l + 32) * 65 + d];
        float v0 = wv_s[l * 65 + d], v1 = wv_s[(l + 32) * 65 + d];
#pragma unroll
        for (int i = 0; i < 4; i++) {
            aq[i][0] += xv[i] * q0; aq[i][1] += xv[i] * q1;
            ak[i][0] += xv[i] * k0; ak[i][1] += xv[i] * k1;
            av[i][0] += xv[i] * v0; av[i][1] += xv[i] * v1;
        }
    }
#pragma unroll
    for (int i = 0; i < 4; i++) {
        int R = (int)R0 + w * 4 + i;
        int n = R / (Pp * Hh);
        int rem = R % (Pp * Hh);
        int p = rem / Hh, h = rem % Hh;
        size_t base = ((size_t)(n * Hh + h) * Pp + p) * HD;
#pragma unroll
        for (int c = 0; c < 2; c++) {
            size_t ix = base + l + c * 32;
            g_q[ix] = __float2half_rn(aq[i][c] * SQS);
            g_k[ix] = __float2half_rn(ak[i][c] * SQS);
            g_v[ix] = __float2half_rn(av[i][c]);
        }
    }
}

// ---- Kernel 2: fused HMMA attention (128 q-rows/CTA, cp.async pipeline) --
// 256 threads = 8 warps; warp w owns q-rows q0+w*16 .. +15.
// smem: double-buffered K,V chunks (128 kv-rows x 64), rows padded to 72 halves.
#define SROW 72
#define BUFH (128 * SROW)   // halves per K or V buffer

__global__ void __launch_bounds__(256, 2) attn_hmma_kernel() {
    extern __shared__ __half sh[];
    // layout: [buf0K | buf0V | buf1K | buf1V]
    int t = threadIdx.x;
    int w = t >> 5, l = t & 31;
    int bx = blockIdx.x;
    int qt = bx & 15, h = (bx >> 4) & 7, n = bx >> 7;
    int nh = n * Hh + h;
    int q0 = qt * 128;
    int g = l >> 2, tq = l & 3;

    uint32_t sbase = s2u(sh);

    // ---- stage Q tile (128 rows) into buf0 K area, build A-frags ----
    {
        const __half* qh = g_q + ((size_t)nh * Pp + q0) * HD;
#pragma unroll
        for (int i = 0; i < 4; i++) {
            int idx = t + i * 256;
            int row = idx >> 3, cg = idx & 7;
            *(uint4*)(sh + row * SROW + cg * 8) = *(const uint4*)(qh + row * 64 + cg * 8);
        }
    }
    __syncthreads();
    uint32_t qf[4][4];
    {
        int arow = w * 16 + (l & 7) + ((l >> 3) & 1) * 8;
        int acol = (l >> 4) * 8;
#pragma unroll
        for (int s = 0; s < 4; s++)
            ldsm4(qf[s], sbase + (uint32_t)((arow * SROW + s * 16 + acol) * 2));
    }
    __syncthreads();

    const __half* kg = g_k + (size_t)nh * Pp * HD;
    const __half* vg = g_v + (size_t)nh * Pp * HD;

    // preload chunk 0 into buffer 0
    {
        uint32_t sK = sbase, sV = sbase + BUFH * 2;
#pragma unroll
        for (int i = 0; i < 4; i++) {
            int idx = t + i * 256;
            int row = idx >> 3, cg = idx & 7;
            uint32_t so = (uint32_t)((row * SROW + cg * 8) * 2);
            size_t go = (size_t)row * 64 + cg * 8;
            cpasync16(sK + so, kg + go);
            cpasync16(sV + so, vg + go);
        }
    }
    CP_COMMIT();

    float dacc[8][4];
#pragma unroll
    for (int i = 0; i < 8; i++)
#pragma unroll
        for (int j = 0; j < 4; j++) dacc[i][j] = 0.0f;
    float rs0 = 0.0f, rs1 = 0.0f;

    int rowE0 = q0 + w * 16 + g;
    __half* eslab = g_E + (size_t)nh * Pp * (size_t)Pp;

    for (int c = 0; c < 16; c++) {
        int cb = c & 1;
        uint32_t bK = sbase + (uint32_t)(cb * 2 * BUFH * 2);
        uint32_t bV = bK + (uint32_t)(BUFH * 2);

        // prefetch chunk c+1 into the other buffer
        if (c < 15) {
            int c1 = (c + 1) * 128;
            uint32_t pK = sbase + (uint32_t)((cb ^ 1) * 2 * BUFH * 2);
            uint32_t pV = pK + (uint32_t)(BUFH * 2);
#pragma unroll
            for (int i = 0; i < 4; i++) {
                int idx = t + i * 256;
                int row = idx >> 3, cg = idx & 7;
                uint32_t so = (uint32_t)((row * SROW + cg * 8) * 2);
                size_t go = (size_t)(c1 + row) * 64 + cg * 8;
                cpasync16(pK + so, kg + go);
                cpasync16(pV + so, vg + go);
            }
            CP_COMMIT();
            CP_WAIT1();
        } else {
            CP_WAIT0();
        }
        __syncthreads();

        int c0 = c * 128;
#pragma unroll
        for (int nhf = 0; nhf < 2; nhf++) {
            // ---- QK^T for 64 kv cols ----
            float cc[8][4];
#pragma unroll
            for (int i = 0; i < 8; i++)
#pragma unroll
                for (int j2 = 0; j2 < 4; j2++) cc[i][j2] = 0.0f;

#pragma unroll
            for (int j = 0; j < 8; j++) {
                int lrow = nhf * 64 + j * 8 + (l & 7);
                int lcol = ((l >> 3) & 3) * 8;
                uint32_t off = (uint32_t)((lrow * SROW + lcol) * 2);
                uint32_t kh[4], kh2[4];
                ldsm4(kh, bK + off);
                ldsm4(kh2, bK + off + 64);
#pragma unroll
                for (int s = 0; s < 4; s++) {
                    uint32_t b0 = (s < 2) ? kh[(s & 1) * 2]     : kh2[(s & 1) * 2];
                    uint32_t b1 = (s < 2) ? kh[(s & 1) * 2 + 1] : kh2[(s & 1) * 2 + 1];
                    mma16816(cc[j], qf[s], b0, b1);
                }
            }

            // ---- exp epilogue: fp16 E store + P frags ----
            uint32_t pf[4][4];
#pragma unroll
            for (int j = 0; j < 8; j++) {
                float v0 = ex2m(cc[j][0]);
                float v1 = ex2m(cc[j][1]);
                float v2 = ex2m(cc[j][2]);
                float v3 = ex2m(cc[j][3]);
                rs0 += v0 + v1;
                rs1 += v2 + v3;
                __half2 h01 = __floats2half2_rn(v0, v1);
                __half2 h23 = __floats2half2_rn(v2, v3);
                int col = c0 + nhf * 64 + j * 8 + 2 * tq;
                *(__half2*)(eslab + (size_t)rowE0 * Pp + col)       = h01;
                *(__half2*)(eslab + (size_t)(rowE0 + 8) * Pp + col) = h23;
                int s = j >> 1, rp = (j & 1) * 2;
                pf[s][rp]     = *(uint32_t*)&h01;
                pf[s][rp + 1] = *(uint32_t*)&h23;
            }

            // ---- AV accumulate (P fp16 x V fp16) ----
#pragma unroll
            for (int s = 0; s < 4; s++) {
                int lrow = nhf * 64 + s * 16 + (l & 7) + ((l >> 3) & 1) * 8;
#pragma unroll
                for (int djp = 0; djp < 4; djp++) {
                    int dj = djp * 2;
                    int lcol = dj * 8 + (l >> 4) * 8;
                    uint32_t off = (uint32_t)((lrow * SROW + lcol) * 2);
                    uint32_t vh[4];
                    ldsm4t(vh, bV + off);
                    mma16816(dacc[dj],     pf[s], vh[0], vh[1]);
                    mma16816(dacc[dj + 1], pf[s], vh[2], vh[3]);
                }
            }
        }
        __syncthreads();
    }

    // ---- finalize: rowsums, inv, oh fp16 store ----
    rs0 += __shfl_xor_sync(0xffffffffu, rs0, 1);
    rs0 += __shfl_xor_sync(0xffffffffu, rs0, 2);
    rs1 += __shfl_xor_sync(0xffffffffu, rs1, 1);
    rs1 += __shfl_xor_sync(0xffffffffu, rs1, 2);
    float inv0 = 1.0f / rs0, inv1 = 1.0f / rs1;
    if (tq == 0) {
        g_inv[nh * Pp + rowE0]     = inv0;
        g_inv[nh * Pp + rowE0 + 8] = inv1;
    }
    size_t ob0 = ((size_t)n * Pp + rowE0) * Dd + h * HD;
    size_t ob1 = ((size_t)n * Pp + rowE0 + 8) * Dd + h * HD;
#pragma unroll
    for (int dj = 0; dj < 8; dj++) {
        int cold = dj * 8 + 2 * tq;
        *(__half2*)(g_oh + ob0 + cold) =
            __floats2half2_rn(dacc[dj][0] * inv0, dacc[dj][1] * inv0);
        *(__half2*)(g_oh + ob1 + cold) =
            __floats2half2_rn(dacc[dj][2] * inv1, dacc[dj][3] * inv1);
    }
}

// ---- Kernel 3: normalize fp16 E -> fp32 attention (streaming) ----------
__global__ void norm_kernel(float* __restrict__ attn) {
    size_t i = ((size_t)blockIdx.x * 256 + threadIdx.x) * 8;
    float inv = g_inv[i >> 11];
    uint4 hraw = __ldcs((const uint4*)(g_E + i));
    __half2* hp = (__half2*)&hraw;
    float4 o0, o1;
    float2 f;
    f = __half22float2(hp[0]); o0.x = f.x * inv; o0.y = f.y * inv;
    f = __half22float2(hp[1]); o0.z = f.x * inv; o0.w = f.y * inv;
    f = __half22float2(hp[2]); o1.x = f.x * inv; o1.y = f.y * inv;
    f = __half22float2(hp[3]); o1.z = f.x * inv; o1.w = f.y * inv;
    __stcs((float4*)(attn + i), o0);
    __stcs((float4*)(attn + i + 4), o1);
}

// ---- Kernel 4a: Wo transpose -> fp16 -----------------------------------
__global__ void woT_kernel(const float* __restrict__ Wo) {
    __shared__ float tile[32][33];
    int x0 = blockIdx.x * 32, y0 = blockIdx.y * 32;
    int tx = threadIdx.x, ty = threadIdx.y;
#pragma unroll
    for (int i = 0; i < 32; i += 8)
        tile[ty + i][tx] = Wo[(size_t)(y0 + ty + i) * Dd + x0 + tx];
    __syncthreads();
#pragma unroll
    for (int i = 0; i < 32; i += 8)
        g_woT[(size_t)(x0 + ty + i) * Dd + y0 + tx] = __float2half_rn(tile[tx][ty + i]);
}

// ---- Kernel 4b: out = oh @ Wo^T + bo (fp16 HMMA) -----------------------
__global__ void __launch_bounds__(128) out_kernel(const float* __restrict__ bo,
                                                  float* __restrict__ out) {
    __shared__ __half sA[64 * SROW];
    __shared__ __half sB[64 * SROW];
    uint32_t bA = s2u(sA), bB = s2u(sB);

    int t = threadIdx.x;
    int w = t >> 5, l = t & 31;
    int ct = blockIdx.x & 7;
    int rt = blockIdx.x >> 3;
    int r0 = rt * 64, e0 = ct * 64;

    float dacc[8][4];
#pragma unroll
    for (int i = 0; i < 8; i++)
#pragma unroll
        for (int j = 0; j < 4; j++) dacc[i][j] = 0.0f;

    for (int kc = 0; kc < Dd; kc += 64) {
        __syncthreads();
#pragma unroll
        for (int i = 0; i < 4; i++) {
            int idx = t + i * 128;
            int row = idx >> 3, cg = (idx & 7) * 8;
            int so = row * SROW + cg;
            *(uint4*)(sA + so) = *(const uint4*)(g_oh + (size_t)(r0 + row) * Dd + kc + cg);
            *(uint4*)(sB + so) = *(const uint4*)(g_woT + (size_t)(kc + row) * Dd + e0 + cg);
        }
        __syncthreads();

        uint32_t af[4][4];
        int arow = w * 16 + (l & 7) + ((l >> 3) & 1) * 8;
        int acol = (l >> 4) * 8;
#pragma unroll
        for (int s = 0; s < 4; s++) {
            uint32_t off = (uint32_t)((arow * SROW + s * 16 + acol) * 2);
            ldsm4(af[s], bA + off);
        }
#pragma unroll
        for (int s = 0; s < 4; s++) {
            int lrow = s * 16 + (l & 7) + ((l >> 3) & 1) * 8;
#pragma unroll
            for (int djp = 0; djp < 4; djp++) {
                int dj = djp * 2;
                int lcol = dj * 8 + (l >> 4) * 8;
                uint32_t off = (uint32_t)((lrow * SROW + lcol) * 2);
                uint32_t bh[4];
                ldsm4t(bh, bB + off);
                mma16816(dacc[dj],     af[s], bh[0], bh[1]);
                mma16816(dacc[dj + 1], af[s], bh[2], bh[3]);
            }
        }
    }

    int g = l >> 2, tq = l & 3;
    int row0 = r0 + w * 16 + g, row1 = row0 + 8;
#pragma unroll
    for (int dj = 0; dj < 8; dj++) {
        int col = e0 + dj * 8 + 2 * tq;
        float2 bias = *(const float2*)(bo + col);
        *(float2*)(out + (size_t)row0 * Dd + col) =
            make_float2(dacc[dj][0] + bias.x, dacc[dj][1] + bias.y);
        *(float2*)(out + (size_t)row1 * Dd + col) =
            make_float2(dacc[dj][2] + bias.x, dacc[dj][3] + bias.y);
    }
}

extern "C" void kernel_launch(void* const* d_in, const int* in_sizes, int n_in,
                              void* d_out, int out_size) {
    const float* xyz = (const float*)d_in[0];
    const float* Wq  = (const float*)d_in[1];
    const float* Wk  = (const float*)d_in[2];
    const float* Wv  = (const float*)d_in[3];
    const float* Wo  = (const float*)d_in[4];
    const float* bo  = (const float*)d_in[5];
    float* out  = (float*)d_out;                          // (4,2048,512)
    float* attn = (float*)d_out + (size_t)Nn * Pp * Dd;   // (4,8,2048,2048)

    static const int QKV_SMEM  = (3 * 64 * 65 + 32 * 64) * 4;
    static const int ATTN_SMEM = 4 * BUFH * 2;            // 73728 B (2 bufs x K,V)
    cudaFuncSetAttribute(qkv_kernel, cudaFuncAttributeMaxDynamicSharedMemorySize, QKV_SMEM);
    cudaFuncSetAttribute(attn_hmma_kernel, cudaFuncAttributeMaxDynamicSharedMemorySize, ATTN_SMEM);

    woT_kernel<<<dim3(16, 16), dim3(32, 8)>>>(Wo);
    qkv_kernel<<<(Nn * Pp * Hh) / 32, 256, QKV_SMEM>>>(xyz, Wq, Wk, Wv);
    attn_hmma_kernel<<<Nn * Hh * (Pp / 128), 256, ATTN_SMEM>>>();
    norm_kernel<<<(int)(((size_t)Nn * Hh * Pp * Pp) / 8 / 256), 256>>>(attn);
    out_kernel<<<(Nn * Pp / 64) * (Dd / 64), 128>>>(bo, out);
}